// round 10
// baseline (speedup 1.0000x reference)
#include <cuda_runtime.h>
#include <cuda_fp16.h>

#define S_TOT 2048
#define B_DIM 64
#define N_DIM 256
#define EPSV 0.01f
#define INV_EPS 100.0f
#define THRESH 0.1f
#define MAX_ITER 100
#define LOG_EPS 1e-8f
#define THREADS 512
#define INIT_BLOCKS 16

// E0_ij = exp((Cmin - C_ij)/eps) in fp16; row sums (of fp16 values) in fp32.
__device__ __align__(16) __half g_E0h[B_DIM * N_DIM];
__device__ float g_logS[B_DIM];
__device__ float g_invS[B_DIM];
__device__ float g_Cmin;
__device__ int   g_ready;   // zero-init; sticky across graph replays (benign:
                            // re-init rewrites byte-identical data)

// smem layout (float offsets); E0h occupies floats [0,8192) as half[16384].
#define O_EUWT  8192    // float4[64]: (eu0, wt0, eu1, wt1)
#define O_SPART 8448    // spartA float4[384] @8448, spartB float4[384] @9984
#define O_SNU   11520   // snu0 [256], snu1 [256]
#define O_SEV   12032   // sev0 [256], sev1 [256]
#define O_SU    12544   // 2 x 64
#define O_SLM   12672   // 2 x 64
#define O_SMU   12800   // 2 x 64
#define O_SRED  12928   // 2 x 32: [0..3]=mv partials, [8..15]=du partials,
                        //         [16..23]=u-max partials, [24]=m_v carry
#define SMEM_FLOATS 12992

#define MAX8(a) fmaxf(fmaxf(fmaxf((a)[0],(a)[1]),fmaxf((a)[2],(a)[3])), \
                      fmaxf(fmaxf((a)[4],(a)[5]),fmaxf((a)[6],(a)[7])))
#define SUM8(a) ((((a)[0]+(a)[1])+((a)[2]+(a)[3]))+(((a)[4]+(a)[5])+((a)[6]+(a)[7])))

// ---------------------------------------------------------------------------
// Single kernel. Blocks 0..15 first build cmin/E0h/rowsums from C, then every
// block (incl. init blocks) waits on g_ready, stages E0h, and runs Sinkhorn
// on its 2 samples.
// ---------------------------------------------------------------------------
extern "C" __global__ void __launch_bounds__(THREADS, 3)
ot_main_kernel(const float* __restrict__ mu,
               const float* __restrict__ nu,
               const float* __restrict__ C,
               float* __restrict__ out) {
    extern __shared__ float sm[];
    __half* sE0h = reinterpret_cast<__half*>(sm);

    const int tid = threadIdx.x;
    const int h   = tid >> 8;          // sample slot
    const int col = tid & 255;
    const int l   = tid & 31;
    const int w   = tid >> 5;          // 0..15
    const int ws  = w & 7;
    const int qr  = tid >> 7;          // row-quarter (v mapping)
    const int cp  = tid & 127;         // col-pair

    // ---------------- fused init (blocks 0..15) ----------------
    if (blockIdx.x < INIT_BLOCKS) {
        float mn = 3.402823466e38f;
        const float4* C4 = reinterpret_cast<const float4*>(C);
        #pragma unroll
        for (int k = 0; k < 8; k++) {
            const float4 c = C4[tid + THREADS * k];
            mn = fminf(mn, fminf(fminf(c.x, c.y), fminf(c.z, c.w)));
        }
        #pragma unroll
        for (int o = 16; o; o >>= 1)
            mn = fminf(mn, __shfl_xor_sync(0xFFFFFFFFu, mn, o));
        if (l == 0) sm[w] = mn;
        __syncthreads();
        if (tid == 0) {
            float t = sm[0];
            #pragma unroll
            for (int k = 1; k < 16; k++) t = fminf(t, sm[k]);
            sm[16] = t;
            g_Cmin = t;                // all init blocks write the same value
        }
        __syncthreads();
        const float cm = sm[16];
        #pragma unroll
        for (int p = 0; p < 2; p++) {  // 512 threads cover 2 rows per pass
            const int row = blockIdx.x * 4 + p * 2 + h;
            const float val = __expf((cm - C[(row << 8) + col]) * INV_EPS);
            const __half hv = __float2half_rn(val);
            g_E0h[(row << 8) + col] = hv;
            float f = __half2float(hv);
            #pragma unroll
            for (int o = 16; o; o >>= 1)
                f += __shfl_xor_sync(0xFFFFFFFFu, f, o);
            if (l == 0) sm[17 + w] = f;
            __syncthreads();
            if (col == 0) {            // tid 0 and 256: one per row
                float s = 0.0f;
                #pragma unroll
                for (int k = 0; k < 8; k++) s += sm[17 + h * 8 + k];
                g_logS[row] = __logf(s);
                g_invS[row] = 1.0f / s;
            }
            __syncthreads();
        }
        __threadfence();
        if (tid == 0) atomicAdd(&g_ready, 1);
    }

    // ---- per-sample inputs (independent of init; overlaps the wait) ----
    const int s0 = blockIdx.x * 2, s1 = s0 + 1, s_h = s0 + h;
    float* su_h   = sm + O_SU  + (h << 6);
    float* slm_h  = sm + O_SLM + (h << 6);
    float* smu_h  = sm + O_SMU + (h << 6);
    float* sred0  = sm + O_SRED;
    float* sred1  = sm + O_SRED + 32;
    float* sred_h = sm + O_SRED + (h << 5);
    float* snu0   = sm + O_SNU;
    float* snu1   = sm + O_SNU + 256;
    float* sev_h  = sm + O_SEV + (h << 8);
    float4* spartA = reinterpret_cast<float4*>(sm + O_SPART);
    float4* spartB = spartA + 384;

    if (col < B_DIM) {
        const float m = mu[s_h * B_DIM + col];
        smu_h[col] = m;
        slm_h[col] = __logf(m + LOG_EPS);
    }
    sm[O_SNU + (h << 8) + col] = EPSV * __logf(nu[s_h * N_DIM + col] + LOG_EPS);
    if (tid == 256) { sred0[24] = 0.0f; sred1[24] = 0.0f; }

    // ---------------- wait for init ----------------
    if (tid == 0) {
        while (*(volatile int*)&g_ready < INIT_BLOCKS) __nanosleep(64);
        __threadfence();
    }
    __syncthreads();

    // ---- stage E0h (32KB, uint4) ----
    {
        const uint4* g4 = reinterpret_cast<const uint4*>(g_E0h);
        uint4* s4 = reinterpret_cast<uint4*>(sE0h);
        #pragma unroll
        for (int k = 0; k < 4; k++)
            s4[tid + THREADS * k] = g4[tid + THREADS * k];
    }
    const float cmin = g_Cmin;
    __syncthreads();

    bool active0 = true, active1 = true;

    for (int it = 0; it < MAX_ITER; ++it) {
        const bool act_h = h ? active1 : active0;

        // ---- u phase (err/m_u partials fused into the pass) ----
        if (it == 0) {
            if (col < B_DIM) {
                const float u1 = EPSV * (slm_h[col] - g_logS[col]) + cmin;
                su_h[col] = u1;
                float d = fabsf(u1);
                #pragma unroll
                for (int o = 16; o; o >>= 1)
                    d += __shfl_xor_sync(0xFFFFFFFFu, d, o);
                if (l == 0) sred_h[8 + ws] = d;   // ws = 0,1 at it0
            }
        } else if (act_h) {
            const float m_v_h = sred_h[24];
            const float4 evA = reinterpret_cast<const float4*>(sev_h)[2 * l];
            const float4 evB = reinterpret_cast<const float4*>(sev_h)[2 * l + 1];
            float myDu = 0.0f;
            float myU  = -3.402823466e38f;
            #pragma unroll
            for (int r = 0; r < 8; ++r) {
                const int row = (ws << 3) + r;
                const int4 hv = reinterpret_cast<const int4*>(sE0h + (row << 8))[l];
                const __half2* hp = reinterpret_cast<const __half2*>(&hv);
                const float2 f0 = __half22float2(hp[0]);
                const float2 f1 = __half22float2(hp[1]);
                const float2 f2 = __half22float2(hp[2]);
                const float2 f3 = __half22float2(hp[3]);
                float p = f0.x * evA.x + f0.y * evA.y + f1.x * evA.z + f1.y * evA.w
                        + f2.x * evB.x + f2.y * evB.y + f3.x * evB.z + f3.y * evB.w;
                #pragma unroll
                for (int o = 16; o; o >>= 1)
                    p += __shfl_xor_sync(0xFFFFFFFFu, p, o);
                if (l == r) {
                    const float unew = EPSV * slm_h[row] - (m_v_h - cmin)
                                     - EPSV * __logf(p);
                    myDu = fabsf(unew - su_h[row]);
                    myU  = unew;
                    su_h[row] = unew;
                }
            }
            #pragma unroll
            for (int o = 16; o; o >>= 1) {
                myDu += __shfl_xor_sync(0xFFFFFFFFu, myDu, o);
                myU   = fmaxf(myU, __shfl_xor_sync(0xFFFFFFFFu, myU, o));
            }
            if (l == 0) { sred_h[8 + ws] = myDu; sred_h[16 + ws] = myU; }
        }
        __syncthreads();                                        // B1

        // ---- err / last flags (broadcast reads; no reduce phase) ----
        float err0, err1;
        if (it == 0) {
            err0 = sred0[8] + sred0[9];
            err1 = sred1[8] + sred1[9];
        } else {
            err0 = SUM8(sred0 + 8);
            err1 = SUM8(sred1 + 8);
        }
        const bool last0 = active0 && (err0 < THRESH || it == MAX_ITER - 1);
        const bool last1 = active1 && (err1 < THRESH || it == MAX_ITER - 1);
        const bool anyLast = last0 || last1;

        // ---- euwt: (eu0, wt0, eu1, wt1) per row ----
        if (col < B_DIM && act_h) {
            float eu;
            if (it == 0) {
                eu = (smu_h[col] + LOG_EPS) * g_invS[col];
            } else {
                const float mu_ = MAX8(sred_h + 16);
                eu = __expf((su_h[col] - mu_) * INV_EPS);
            }
            float* qp = sm + O_EUWT + (col << 2);
            qp[2 * h]     = eu;
            qp[2 * h + 1] = eu * smu_h[col];
        }
        __syncthreads();                                        // B3

        const __half2* cph = reinterpret_cast<const __half2*>(sE0h)
                           + (qr << 11) + cp;
        const float4* qw = reinterpret_cast<const float4*>(sm + O_EUWT) + (qr << 4);

        if (!anyLast) {
            // ===== LIGHT v-pass: av only, single-float4 exchange =====
            float av0a = 0, av0b = 0, av1a = 0, av1b = 0;
            #pragma unroll
            for (int i = 0; i < 16; i++) {
                const float2 cf = __half22float2(cph[i << 7]);
                const float4 q  = qw[i];
                av0a = fmaf(cf.x, q.x, av0a); av0b = fmaf(cf.y, q.x, av0b);
                av1a = fmaf(cf.x, q.z, av1a); av1b = fmaf(cf.y, q.z, av1b);
            }
            if (qr) spartA[((qr - 1) << 7) + cp] = make_float4(av0a, av0b, av1a, av1b);
            __syncthreads();                                    // B4
            if (qr == 0) {
                #pragma unroll
                for (int t = 0; t < 3; t++) {
                    const float4 pa = spartA[(t << 7) + cp];
                    av0a += pa.x; av0b += pa.y; av1a += pa.z; av1b += pa.w;
                }
                const float2 ln0 = *reinterpret_cast<const float2*>(snu0 + 2 * cp);
                const float2 ln1 = *reinterpret_cast<const float2*>(snu1 + 2 * cp);
                const float mue0 = (it == 0) ? cmin : MAX8(sred0 + 16);
                const float mue1 = (it == 0) ? cmin : MAX8(sred1 + 16);
                const float v0a = ln0.x - (mue0 - cmin) - EPSV * __logf(av0a);
                const float v0b = ln0.y - (mue0 - cmin) - EPSV * __logf(av0b);
                const float v1a = ln1.x - (mue1 - cmin) - EPSV * __logf(av1a);
                const float v1b = ln1.y - (mue1 - cmin) - EPSV * __logf(av1b);
                float m0 = fmaxf(v0a, v0b);
                float m1 = fmaxf(v1a, v1b);
                #pragma unroll
                for (int o = 16; o; o >>= 1) {
                    m0 = fmaxf(m0, __shfl_xor_sync(0xFFFFFFFFu, m0, o));
                    m1 = fmaxf(m1, __shfl_xor_sync(0xFFFFFFFFu, m1, o));
                }
                if (l == 0) { sred0[w] = m0; sred1[w] = m1; }   // w = 0..3
                asm volatile("bar.sync 1, 128;" ::: "memory");  // B5 (named)
                m0 = fmaxf(fmaxf(sred0[0], sred0[1]), fmaxf(sred0[2], sred0[3]));
                m1 = fmaxf(fmaxf(sred1[0], sred1[1]), fmaxf(sred1[2], sred1[3]));
                if (active0) {
                    *reinterpret_cast<float2*>(sm + O_SEV + 2 * cp)
                        = make_float2(__expf((v0a - m0) * INV_EPS),
                                      __expf((v0b - m0) * INV_EPS));
                    if (tid == 0) sred0[24] = m0;
                }
                if (active1) {
                    *reinterpret_cast<float2*>(sm + O_SEV + 256 + 2 * cp)
                        = make_float2(__expf((v1a - m1) * INV_EPS),
                                      __expf((v1b - m1) * INV_EPS));
                    if (tid == 0) sred1[24] = m1;
                }
            }
            __syncthreads();                                    // B6
        } else {
            // ===== FULL v-pass: av+ae, outputs written on last iteration =====
            float av0a = 0, av0b = 0, ae0a = 0, ae0b = 0;
            float av1a = 0, av1b = 0, ae1a = 0, ae1b = 0;
            #pragma unroll
            for (int i = 0; i < 16; i++) {
                const float2 cf = __half22float2(cph[i << 7]);
                const float4 q  = qw[i];
                av0a = fmaf(cf.x, q.x, av0a); av0b = fmaf(cf.y, q.x, av0b);
                ae0a = fmaf(cf.x, q.y, ae0a); ae0b = fmaf(cf.y, q.y, ae0b);
                av1a = fmaf(cf.x, q.z, av1a); av1b = fmaf(cf.y, q.z, av1b);
                ae1a = fmaf(cf.x, q.w, ae1a); ae1b = fmaf(cf.y, q.w, ae1b);
            }
            if (qr) {
                spartA[((qr - 1) << 7) + cp] = make_float4(av0a, ae0a, av1a, ae1a);
                spartB[((qr - 1) << 7) + cp] = make_float4(av0b, ae0b, av1b, ae1b);
            }
            __syncthreads();                                    // B4
            if (qr == 0) {
                #pragma unroll
                for (int t = 0; t < 3; t++) {
                    const float4 pa = spartA[(t << 7) + cp];
                    const float4 pb = spartB[(t << 7) + cp];
                    av0a += pa.x; ae0a += pa.y; av1a += pa.z; ae1a += pa.w;
                    av0b += pb.x; ae0b += pb.y; av1b += pb.z; ae1b += pb.w;
                }
                const float2 ln0 = *reinterpret_cast<const float2*>(snu0 + 2 * cp);
                const float2 ln1 = *reinterpret_cast<const float2*>(snu1 + 2 * cp);
                const float mue0 = (it == 0) ? cmin : MAX8(sred0 + 16);
                const float mue1 = (it == 0) ? cmin : MAX8(sred1 + 16);
                const float v0a = ln0.x - (mue0 - cmin) - EPSV * __logf(av0a);
                const float v0b = ln0.y - (mue0 - cmin) - EPSV * __logf(av0b);
                const float v1a = ln1.x - (mue1 - cmin) - EPSV * __logf(av1a);
                const float v1b = ln1.y - (mue1 - cmin) - EPSV * __logf(av1b);
                float m0 = fmaxf(v0a, v0b);
                float m1 = fmaxf(v1a, v1b);
                #pragma unroll
                for (int o = 16; o; o >>= 1) {
                    m0 = fmaxf(m0, __shfl_xor_sync(0xFFFFFFFFu, m0, o));
                    m1 = fmaxf(m1, __shfl_xor_sync(0xFFFFFFFFu, m1, o));
                }
                if (l == 0) { sred0[w] = m0; sred1[w] = m1; }
                asm volatile("bar.sync 1, 128;" ::: "memory");  // B5 (named)
                m0 = fmaxf(fmaxf(sred0[0], sred0[1]), fmaxf(sred0[2], sred0[3]));
                m1 = fmaxf(fmaxf(sred1[0], sred1[1]), fmaxf(sred1[2], sred1[3]));
                if (active0) {
                    const float e0a = __expf((v0a - m0) * INV_EPS);
                    const float e0b = __expf((v0b - m0) * INV_EPS);
                    *reinterpret_cast<float2*>(sm + O_SEV + 2 * cp)
                        = make_float2(e0a, e0b);
                    if (tid == 0) sred0[24] = m0;
                    if (last0) {
                        const float sc = __expf((mue0 + m0 - cmin) * INV_EPS);
                        *reinterpret_cast<float2*>(out + s0 * N_DIM + 2 * cp)
                            = make_float2(sc * e0a * ae0a, sc * e0b * ae0b);
                    }
                }
                if (active1) {
                    const float e1a = __expf((v1a - m1) * INV_EPS);
                    const float e1b = __expf((v1b - m1) * INV_EPS);
                    *reinterpret_cast<float2*>(sm + O_SEV + 256 + 2 * cp)
                        = make_float2(e1a, e1b);
                    if (tid == 0) sred1[24] = m1;
                    if (last1) {
                        const float sc = __expf((mue1 + m1 - cmin) * INV_EPS);
                        *reinterpret_cast<float2*>(out + s1 * N_DIM + 2 * cp)
                            = make_float2(sc * e1a * ae1a, sc * e1b * ae1b);
                    }
                }
            }
            __syncthreads();                                    // B6
        }

        if (last0) active0 = false;
        if (last1) active1 = false;
        if (!active0 && !active1) break;
    }
}

// ---------------------------------------------------------------------------
// Launch — single kernel.
// ---------------------------------------------------------------------------
extern "C" void kernel_launch(void* const* d_in, const int* in_sizes, int n_in,
                              void* d_out, int out_size) {
    const float* mu = nullptr;
    const float* nu = nullptr;
    const float* C  = nullptr;
    for (int i = 0; i < n_in; ++i) {
        if (in_sizes[i] == S_TOT * B_DIM)      mu = (const float*)d_in[i];
        else if (in_sizes[i] == S_TOT * N_DIM) nu = (const float*)d_in[i];
        else if (in_sizes[i] == B_DIM * N_DIM) C  = (const float*)d_in[i];
    }
    float* out = (float*)d_out;

    const int smem_bytes = SMEM_FLOATS * sizeof(float);   // ~50.8 KB, 3 blk/SM
    cudaFuncSetAttribute(ot_main_kernel,
                         cudaFuncAttributeMaxDynamicSharedMemorySize, smem_bytes);

    ot_main_kernel<<<S_TOT / 2, THREADS, smem_bytes>>>(mu, nu, C, out);
}

// round 11
// speedup vs baseline: 1.0548x; 1.0548x over previous
#include <cuda_runtime.h>
#include <cuda_fp16.h>

#define S_TOT 2048
#define B_DIM 64
#define N_DIM 256
#define EPSV 0.01f
#define INV_EPS 100.0f
#define THRESH 0.1f
#define MAX_ITER 100
#define LOG_EPS 1e-8f
#define THREADS 512

// E0_ij = exp((Cmin - C_ij)/eps) in fp16; row sums (of fp16 values) in fp32.
__device__ __align__(16) __half g_E0h[B_DIM * N_DIM];
__device__ float g_logS[B_DIM];
__device__ float g_invS[B_DIM];
__device__ float g_Cmin;

// ---------------------------------------------------------------------------
// Init: 16 blocks x 256 threads (proven ~0.7us). Every block redundantly
// computes cmin; block b builds rows 4b..4b+3 of E0h and their row sums.
// ---------------------------------------------------------------------------
__global__ void __launch_bounds__(256) ot_init_kernel(const float* __restrict__ C) {
    __shared__ float sred[9];
    const int tid = threadIdx.x, l = tid & 31, w = tid >> 5;

    float mn = 3.402823466e38f;
    const float4* C4 = reinterpret_cast<const float4*>(C);
    #pragma unroll
    for (int k = 0; k < 16; k++) {
        const float4 c = C4[tid + 256 * k];
        mn = fminf(mn, fminf(fminf(c.x, c.y), fminf(c.z, c.w)));
    }
    #pragma unroll
    for (int o = 16; o; o >>= 1)
        mn = fminf(mn, __shfl_xor_sync(0xFFFFFFFFu, mn, o));
    if (l == 0) sred[w] = mn;
    __syncthreads();
    if (tid == 0) {
        float t = sred[0];
        #pragma unroll
        for (int k = 1; k < 8; k++) t = fminf(t, sred[k]);
        sred[8] = t;
        if (blockIdx.x == 0) g_Cmin = t;
    }
    __syncthreads();
    const float cmin = sred[8];

    #pragma unroll
    for (int rr = 0; rr < 4; rr++) {
        const int row = blockIdx.x * 4 + rr;
        const float val = __expf((cmin - C[(row << 8) + tid]) * INV_EPS);
        const __half hv = __float2half_rn(val);
        g_E0h[(row << 8) + tid] = hv;
        float f = __half2float(hv);
        #pragma unroll
        for (int o = 16; o; o >>= 1)
            f += __shfl_xor_sync(0xFFFFFFFFu, f, o);
        __syncthreads();
        if (l == 0) sred[w] = f;
        __syncthreads();
        if (tid == 0) {
            float s = 0.0f;
            #pragma unroll
            for (int k = 0; k < 8; k++) s += sred[k];
            g_logS[row] = __logf(s);
            g_invS[row] = 1.0f / s;
        }
    }
}

// smem layout (float offsets); E0h occupies floats [0,8192) as half[16384].
#define O_EUWT  8192    // float4[64]: (eu0, wt0, eu1, wt1)
#define O_SPART 8448    // spartA float4[384] @8448, spartB float4[384] @9984
#define O_SNU   11520   // snu0 [256], snu1 [256]
#define O_SEV   12032   // sev0 [256], sev1 [256]
#define O_SU    12544   // 2 x 64
#define O_SLM   12672   // 2 x 64
#define O_SMU   12800   // 2 x 64
#define O_SRED  12928   // 2 x 32: [0..3]=mv partials, [8..15]=du partials,
                        //         [16..23]=u-max partials, [24]=m_v, [25]=m_u
#define SMEM_FLOATS 12992

#define MAX8(a) fmaxf(fmaxf(fmaxf((a)[0],(a)[1]),fmaxf((a)[2],(a)[3])), \
                      fmaxf(fmaxf((a)[4],(a)[5]),fmaxf((a)[6],(a)[7])))
#define SUM8(a) ((((a)[0]+(a)[1])+((a)[2]+(a)[3]))+(((a)[4]+(a)[5])+((a)[6]+(a)[7])))

// ---------------------------------------------------------------------------
// Main: 2 samples/block, 512 threads, fp16 E0 in shared, 3 blocks/SM.
// Restructured: the ENTIRE it0 u-phase (u1/err/euwt from precomputed row
// sums) lives in the prologue, overlapped with E0 staging under one barrier.
// Loop body (uniform, no it==0 branches): v-pass -> break -> u-pass -> euwt.
// m_u is carried in sred[25] (cmin at it0), m_v in sred[24].
// ---------------------------------------------------------------------------
extern "C" __global__ void __launch_bounds__(THREADS, 3)
ot_main_kernel(const float* __restrict__ mu,
               const float* __restrict__ nu,
               float* __restrict__ out) {
    extern __shared__ float sm[];
    __half* sE0h = reinterpret_cast<__half*>(sm);

    const int tid = threadIdx.x;
    const int h   = tid >> 8;          // sample slot
    const int col = tid & 255;
    const int l   = tid & 31;
    const int w   = tid >> 5;          // 0..15
    const int ws  = w & 7;
    const int qr  = tid >> 7;          // row-quarter (v mapping)
    const int cp  = tid & 127;         // col-pair

    float* snu0   = sm + O_SNU;
    float* snu1   = sm + O_SNU + 256;
    float* sev_h  = sm + O_SEV + (h << 8);
    float* su_h   = sm + O_SU  + (h << 6);
    float* slm_h  = sm + O_SLM + (h << 6);
    float* smu_h  = sm + O_SMU + (h << 6);
    float* sred0  = sm + O_SRED;
    float* sred1  = sm + O_SRED + 32;
    float* sred_h = sm + O_SRED + (h << 5);
    float4* spartA = reinterpret_cast<float4*>(sm + O_SPART);
    float4* spartB = spartA + 384;

    const int s0 = blockIdx.x * 2, s1 = s0 + 1, s_h = s0 + h;
    const float cmin = g_Cmin;

    // ================= PROLOGUE (one barrier) =================
    // stage E0h (32KB, uint4)
    {
        const uint4* g4 = reinterpret_cast<const uint4*>(g_E0h);
        uint4* s4 = reinterpret_cast<uint4*>(sE0h);
        #pragma unroll
        for (int k = 0; k < 4; k++)
            s4[tid + THREADS * k] = g4[tid + THREADS * k];
    }
    // inputs + full it0 u-phase (independent of staging)
    sm[O_SNU + (h << 8) + col] = EPSV * __logf(nu[s_h * N_DIM + col] + LOG_EPS);
    if (col < B_DIM) {
        const float m  = mu[s_h * B_DIM + col];
        const float lm = __logf(m + LOG_EPS);
        smu_h[col] = m;
        slm_h[col] = lm;
        const float u1 = EPSV * (lm - g_logS[col]) + cmin;
        su_h[col] = u1;
        // err partials (warps 0,1 per sample half)
        float d = fabsf(u1);
        #pragma unroll
        for (int o = 16; o; o >>= 1)
            d += __shfl_xor_sync(0xFFFFFFFFu, d, o);
        if (l == 0) sred_h[8 + ws] = d;
        // it0 euwt: eu0 = exp((u1 - cmin)/eps) = (mu + 1e-8)/S
        const float eu = (m + LOG_EPS) * g_invS[col];
        float* qp = sm + O_EUWT + (col << 2);
        qp[2 * h]     = eu;
        qp[2 * h + 1] = eu * m;
    }
    if (l == 0 && ws >= 2) sred_h[8 + ws] = 0.0f;   // unused err partials
    if (tid == 0)   { sred0[24] = 0.0f; sred0[25] = cmin; }
    if (tid == 256) { sred1[24] = 0.0f; sred1[25] = cmin; }
    __syncthreads();                                        // P

    bool active0 = true, active1 = true;

    // ================= MAIN LOOP (v -> break -> u -> euwt) =================
    for (int it = 0; it < MAX_ITER; ++it) {
        const float err0 = SUM8(sred0 + 8);
        const float err1 = SUM8(sred1 + 8);
        const bool last0 = active0 && (err0 < THRESH || it == MAX_ITER - 1);
        const bool last1 = active1 && (err1 < THRESH || it == MAX_ITER - 1);
        const bool anyLast = last0 || last1;

        const __half2* cph = reinterpret_cast<const __half2*>(sE0h)
                           + (qr << 11) + cp;
        const float4* qw = reinterpret_cast<const float4*>(sm + O_EUWT) + (qr << 4);

        if (!anyLast) {
            // ===== LIGHT v-pass: av only, single-float4 exchange =====
            float av0a = 0, av0b = 0, av1a = 0, av1b = 0;
            #pragma unroll
            for (int i = 0; i < 16; i++) {
                const float2 cf = __half22float2(cph[i << 7]);
                const float4 q  = qw[i];
                av0a = fmaf(cf.x, q.x, av0a); av0b = fmaf(cf.y, q.x, av0b);
                av1a = fmaf(cf.x, q.z, av1a); av1b = fmaf(cf.y, q.z, av1b);
            }
            if (qr) spartA[((qr - 1) << 7) + cp] = make_float4(av0a, av0b, av1a, av1b);
            __syncthreads();                                    // B4
            if (qr == 0) {
                #pragma unroll
                for (int t = 0; t < 3; t++) {
                    const float4 pa = spartA[(t << 7) + cp];
                    av0a += pa.x; av0b += pa.y; av1a += pa.z; av1b += pa.w;
                }
                const float2 ln0 = *reinterpret_cast<const float2*>(snu0 + 2 * cp);
                const float2 ln1 = *reinterpret_cast<const float2*>(snu1 + 2 * cp);
                const float mue0 = sred0[25];
                const float mue1 = sred1[25];
                const float v0a = ln0.x - (mue0 - cmin) - EPSV * __logf(av0a);
                const float v0b = ln0.y - (mue0 - cmin) - EPSV * __logf(av0b);
                const float v1a = ln1.x - (mue1 - cmin) - EPSV * __logf(av1a);
                const float v1b = ln1.y - (mue1 - cmin) - EPSV * __logf(av1b);
                float m0 = fmaxf(v0a, v0b);
                float m1 = fmaxf(v1a, v1b);
                #pragma unroll
                for (int o = 16; o; o >>= 1) {
                    m0 = fmaxf(m0, __shfl_xor_sync(0xFFFFFFFFu, m0, o));
                    m1 = fmaxf(m1, __shfl_xor_sync(0xFFFFFFFFu, m1, o));
                }
                if (l == 0) { sred0[w] = m0; sred1[w] = m1; }   // w = 0..3
                asm volatile("bar.sync 1, 128;" ::: "memory");  // B5 (named)
                m0 = fmaxf(fmaxf(sred0[0], sred0[1]), fmaxf(sred0[2], sred0[3]));
                m1 = fmaxf(fmaxf(sred1[0], sred1[1]), fmaxf(sred1[2], sred1[3]));
                if (active0) {
                    *reinterpret_cast<float2*>(sm + O_SEV + 2 * cp)
                        = make_float2(__expf((v0a - m0) * INV_EPS),
                                      __expf((v0b - m0) * INV_EPS));
                    if (tid == 0) sred0[24] = m0;
                }
                if (active1) {
                    *reinterpret_cast<float2*>(sm + O_SEV + 256 + 2 * cp)
                        = make_float2(__expf((v1a - m1) * INV_EPS),
                                      __expf((v1b - m1) * INV_EPS));
                    if (tid == 0) sred1[24] = m1;
                }
            }
            __syncthreads();                                    // B6
        } else {
            // ===== FULL v-pass: av+ae, outputs written for last samples =====
            float av0a = 0, av0b = 0, ae0a = 0, ae0b = 0;
            float av1a = 0, av1b = 0, ae1a = 0, ae1b = 0;
            #pragma unroll
            for (int i = 0; i < 16; i++) {
                const float2 cf = __half22float2(cph[i << 7]);
                const float4 q  = qw[i];
                av0a = fmaf(cf.x, q.x, av0a); av0b = fmaf(cf.y, q.x, av0b);
                ae0a = fmaf(cf.x, q.y, ae0a); ae0b = fmaf(cf.y, q.y, ae0b);
                av1a = fmaf(cf.x, q.z, av1a); av1b = fmaf(cf.y, q.z, av1b);
                ae1a = fmaf(cf.x, q.w, ae1a); ae1b = fmaf(cf.y, q.w, ae1b);
            }
            if (qr) {
                spartA[((qr - 1) << 7) + cp] = make_float4(av0a, ae0a, av1a, ae1a);
                spartB[((qr - 1) << 7) + cp] = make_float4(av0b, ae0b, av1b, ae1b);
            }
            __syncthreads();                                    // B4
            if (qr == 0) {
                #pragma unroll
                for (int t = 0; t < 3; t++) {
                    const float4 pa = spartA[(t << 7) + cp];
                    const float4 pb = spartB[(t << 7) + cp];
                    av0a += pa.x; ae0a += pa.y; av1a += pa.z; ae1a += pa.w;
                    av0b += pb.x; ae0b += pb.y; av1b += pb.z; ae1b += pb.w;
                }
                const float2 ln0 = *reinterpret_cast<const float2*>(snu0 + 2 * cp);
                const float2 ln1 = *reinterpret_cast<const float2*>(snu1 + 2 * cp);
                const float mue0 = sred0[25];
                const float mue1 = sred1[25];
                const float v0a = ln0.x - (mue0 - cmin) - EPSV * __logf(av0a);
                const float v0b = ln0.y - (mue0 - cmin) - EPSV * __logf(av0b);
                const float v1a = ln1.x - (mue1 - cmin) - EPSV * __logf(av1a);
                const float v1b = ln1.y - (mue1 - cmin) - EPSV * __logf(av1b);
                float m0 = fmaxf(v0a, v0b);
                float m1 = fmaxf(v1a, v1b);
                #pragma unroll
                for (int o = 16; o; o >>= 1) {
                    m0 = fmaxf(m0, __shfl_xor_sync(0xFFFFFFFFu, m0, o));
                    m1 = fmaxf(m1, __shfl_xor_sync(0xFFFFFFFFu, m1, o));
                }
                if (l == 0) { sred0[w] = m0; sred1[w] = m1; }
                asm volatile("bar.sync 1, 128;" ::: "memory");  // B5 (named)
                m0 = fmaxf(fmaxf(sred0[0], sred0[1]), fmaxf(sred0[2], sred0[3]));
                m1 = fmaxf(fmaxf(sred1[0], sred1[1]), fmaxf(sred1[2], sred1[3]));
                if (active0) {
                    const float e0a = __expf((v0a - m0) * INV_EPS);
                    const float e0b = __expf((v0b - m0) * INV_EPS);
                    *reinterpret_cast<float2*>(sm + O_SEV + 2 * cp)
                        = make_float2(e0a, e0b);
                    if (tid == 0) sred0[24] = m0;
                    if (last0) {
                        const float sc = __expf((mue0 + m0 - cmin) * INV_EPS);
                        *reinterpret_cast<float2*>(out + s0 * N_DIM + 2 * cp)
                            = make_float2(sc * e0a * ae0a, sc * e0b * ae0b);
                    }
                }
                if (active1) {
                    const float e1a = __expf((v1a - m1) * INV_EPS);
                    const float e1b = __expf((v1b - m1) * INV_EPS);
                    *reinterpret_cast<float2*>(sm + O_SEV + 256 + 2 * cp)
                        = make_float2(e1a, e1b);
                    if (tid == 0) sred1[24] = m1;
                    if (last1) {
                        const float sc = __expf((mue1 + m1 - cmin) * INV_EPS);
                        *reinterpret_cast<float2*>(out + s1 * N_DIM + 2 * cp)
                            = make_float2(sc * e1a * ae1a, sc * e1b * ae1b);
                    }
                }
            }
            __syncthreads();                                    // B6
        }

        if (last0) active0 = false;
        if (last1) active1 = false;
        if (!active0 && !active1) break;

        // ---- u-pass for iteration it+1 (fused err/m_u partials) ----
        const bool act_h = h ? active1 : active0;
        if (act_h) {
            const float m_v_h = sred_h[24];
            const float4 evA = reinterpret_cast<const float4*>(sev_h)[2 * l];
            const float4 evB = reinterpret_cast<const float4*>(sev_h)[2 * l + 1];
            float myDu = 0.0f;
            float myU  = -3.402823466e38f;
            #pragma unroll
            for (int r = 0; r < 8; ++r) {
                const int row = (ws << 3) + r;
                const int4 hv = reinterpret_cast<const int4*>(sE0h + (row << 8))[l];
                const __half2* hp = reinterpret_cast<const __half2*>(&hv);
                const float2 f0 = __half22float2(hp[0]);
                const float2 f1 = __half22float2(hp[1]);
                const float2 f2 = __half22float2(hp[2]);
                const float2 f3 = __half22float2(hp[3]);
                float p = f0.x * evA.x + f0.y * evA.y + f1.x * evA.z + f1.y * evA.w
                        + f2.x * evB.x + f2.y * evB.y + f3.x * evB.z + f3.y * evB.w;
                #pragma unroll
                for (int o = 16; o; o >>= 1)
                    p += __shfl_xor_sync(0xFFFFFFFFu, p, o);
                if (l == r) {
                    const float unew = EPSV * slm_h[row] - (m_v_h - cmin)
                                     - EPSV * __logf(p);
                    myDu = fabsf(unew - su_h[row]);
                    myU  = unew;
                    su_h[row] = unew;
                }
            }
            #pragma unroll
            for (int o = 16; o; o >>= 1) {
                myDu += __shfl_xor_sync(0xFFFFFFFFu, myDu, o);
                myU   = fmaxf(myU, __shfl_xor_sync(0xFFFFFFFFu, myU, o));
            }
            if (l == 0) { sred_h[8 + ws] = myDu; sred_h[16 + ws] = myU; }
        }
        __syncthreads();                                        // B1

        // ---- euwt for iteration it+1 ----
        if (col < B_DIM && act_h) {
            const float mu_ = MAX8(sred_h + 16);
            const float eu = __expf((su_h[col] - mu_) * INV_EPS);
            float* qp = sm + O_EUWT + (col << 2);
            qp[2 * h]     = eu;
            qp[2 * h + 1] = eu * smu_h[col];
            if (col == 0) sred_h[25] = mu_;
        }
        __syncthreads();                                        // B3
    }
}

// ---------------------------------------------------------------------------
// Launch
// ---------------------------------------------------------------------------
extern "C" void kernel_launch(void* const* d_in, const int* in_sizes, int n_in,
                              void* d_out, int out_size) {
    const float* mu = nullptr;
    const float* nu = nullptr;
    const float* C  = nullptr;
    for (int i = 0; i < n_in; ++i) {
        if (in_sizes[i] == S_TOT * B_DIM)      mu = (const float*)d_in[i];
        else if (in_sizes[i] == S_TOT * N_DIM) nu = (const float*)d_in[i];
        else if (in_sizes[i] == B_DIM * N_DIM) C  = (const float*)d_in[i];
    }
    float* out = (float*)d_out;

    const int smem_bytes = SMEM_FLOATS * sizeof(float);   // ~50.8 KB, 3 blk/SM
    cudaFuncSetAttribute(ot_main_kernel,
                         cudaFuncAttributeMaxDynamicSharedMemorySize, smem_bytes);

    ot_init_kernel<<<16, 256>>>(C);
    ot_main_kernel<<<S_TOT / 2, THREADS, smem_bytes>>>(mu, nu, out);
}